// round 3
// baseline (speedup 1.0000x reference)
#include <cuda_runtime.h>
#include <cuda_bf16.h>
#include <math.h>

// Problem constants
#define L_TOT 2048
#define B_TOT 32
#define H_TOT 128
#define P_TOT 256
#define T_CHK 64
#define C_CHK (L_TOT / T_CHK)       // 32 chunks
#define M_TOT (L_TOT * B_TOT)       // 65536 rows
#define N1 (2 * P_TOT)              // 512 (interleaved r,i)
#define K1 H_TOT                    // 128
#define K2TOT (2 * P_TOT)           // 512
#define N2 H_TOT                    // 128

// Scratch (device globals: allocation-free rule)
__device__ float2 g_Bu[(size_t)M_TOT * P_TOT];     // 134 MB; later overwritten by o (scan result)
__device__ float2 g_Sloc[C_CHK * B_TOT * P_TOT];   // per-chunk local final states
__device__ float2 g_init[C_CHK * B_TOT * P_TOT];   // per-chunk initial states
__device__ float2 g_Lam[P_TOT];
__device__ float2 g_LamT[P_TOT];
__device__ float  g_W1[K1 * N1];                   // [128][512]: h -> (Bbar_r, Bbar_i) interleaved over p
__device__ float  g_W2[K2TOT * N2];                // [512][128]: (2p)->C_r[h,p], (2p+1)->-C_i[h,p]

// ---------------- K0: precompute Lambda_bar, B_bar, packed weights ----------------
__global__ void precompute_kernel(const float* __restrict__ lLr, const float* __restrict__ Li,
                                  const float* __restrict__ Br, const float* __restrict__ Bi,
                                  const float* __restrict__ Cr, const float* __restrict__ Ci,
                                  const float* __restrict__ lDelta) {
    int p = threadIdx.x;  // 256 threads
    double lamr = -exp((double)lLr[p]);
    double lami = (double)Li[p];
    double dt = exp((double)lDelta[p]);
    double lbr = lamr * dt, lbi = lami * dt;
    double er = exp(lbr);
    double Lr = er * cos(lbi), Limg = er * sin(lbi);
    g_Lam[p] = make_float2((float)Lr, (float)Limg);
    double eT = exp((double)T_CHK * lbr);
    g_LamT[p] = make_float2((float)(eT * cos((double)T_CHK * lbi)),
                            (float)(eT * sin((double)T_CHK * lbi)));
    // coeff = (Lambda_bar - 1) / lam
    double nr = Lr - 1.0, ni = Limg;
    double den = lamr * lamr + lami * lami;
    double ccr = (nr * lamr + ni * lami) / den;
    double cci = (ni * lamr - nr * lami) / den;
    float crf = (float)ccr, cif = (float)cci;
    for (int h = 0; h < H_TOT; h++) {
        float br = Br[p * H_TOT + h], bi = Bi[p * H_TOT + h];
        g_W1[h * N1 + 2 * p]     = crf * br - cif * bi;
        g_W1[h * N1 + 2 * p + 1] = crf * bi + cif * br;
        g_W2[(2 * p) * N2 + h]     = Cr[h * P_TOT + p];
        g_W2[(2 * p + 1) * N2 + h] = -Ci[h * P_TOT + p];
    }
}

// ---------------- SIMT fp32 GEMM: C = A(MxK) * B(KxN), 128x128 block tile ----------------
template <bool EPI>
__global__ __launch_bounds__(256) void gemm128_kernel(
    const float* __restrict__ A, const float* __restrict__ Bm, float* __restrict__ Cout,
    int M, int N, int K, const float* __restrict__ Dv, const float* __restrict__ U) {
    const int BK = 16;
    __shared__ float As[BK][128];
    __shared__ float Bs[BK][128];
    int tid = threadIdx.x;
    int tx = tid & 15, ty = tid >> 4;
    int bn = blockIdx.x * 128;
    int bm = blockIdx.y * 128;
    float acc[8][8];
#pragma unroll
    for (int i = 0; i < 8; i++)
#pragma unroll
        for (int j = 0; j < 8; j++) acc[i][j] = 0.f;

    const float* Ablk = A + (size_t)bm * K;
    const float* Bblk = Bm + bn;

    for (int kt = 0; kt < K; kt += BK) {
        // Load A tile 128x16 (2 float4 per thread), store transposed
#pragma unroll
        for (int i = 0; i < 2; i++) {
            int idx = tid + i * 256;
            int row = idx >> 2, c4 = (idx & 3) * 4;
            float4 v = *(const float4*)(Ablk + (size_t)row * K + kt + c4);
            As[c4 + 0][row] = v.x; As[c4 + 1][row] = v.y;
            As[c4 + 2][row] = v.z; As[c4 + 3][row] = v.w;
        }
        // Load B tile 16x128
#pragma unroll
        for (int i = 0; i < 2; i++) {
            int idx = tid + i * 256;
            int row = idx >> 5, c4 = (idx & 31) * 4;
            *(float4*)&Bs[row][c4] = *(const float4*)(Bblk + (size_t)(kt + row) * N + c4);
        }
        __syncthreads();
#pragma unroll
        for (int kk = 0; kk < BK; kk++) {
            float a[8], b[8];
            *(float4*)&a[0] = *(const float4*)&As[kk][ty * 8];
            *(float4*)&a[4] = *(const float4*)&As[kk][ty * 8 + 4];
            *(float4*)&b[0] = *(const float4*)&Bs[kk][tx * 8];
            *(float4*)&b[4] = *(const float4*)&Bs[kk][tx * 8 + 4];
#pragma unroll
            for (int i = 0; i < 8; i++)
#pragma unroll
                for (int j = 0; j < 8; j++) acc[i][j] += a[i] * b[j];
        }
        __syncthreads();
    }

#pragma unroll
    for (int i = 0; i < 8; i++) {
        int m = bm + ty * 8 + i;
        int ncol = bn + tx * 8;
        float* outp = Cout + (size_t)m * N + ncol;
        if (EPI) {
            const float* up = U + (size_t)m * N + ncol;
#pragma unroll
            for (int j = 0; j < 8; j++) {
                outp[j] = acc[i][j] + Dv[ncol + j] * up[j];
            }
        } else {
            *(float4*)outp = *(float4*)&acc[i][0];
            *(float4*)(outp + 4) = *(float4*)&acc[i][4];
        }
    }
}

// ---------------- Complex helpers ----------------
__device__ __forceinline__ float2 cmul(float2 a, float2 b) {
    return make_float2(a.x * b.x - a.y * b.y, a.x * b.y + a.y * b.x);
}

// ---------------- K2: per-chunk local scan (zero-init final state) ----------------
__global__ __launch_bounds__(256) void scan_local_kernel() {
    int p = threadIdx.x;
    int b = blockIdx.x % B_TOT;
    int c = blockIdx.x / B_TOT;
    float2 lam = g_Lam[p];
    float2 s = make_float2(0.f, 0.f);
    const float2* base = g_Bu + ((size_t)(c * T_CHK) * B_TOT + b) * P_TOT + p;
    const size_t stride = (size_t)B_TOT * P_TOT;
#pragma unroll 4
    for (int t = 0; t < T_CHK; t++) {
        float2 x = base[t * stride];
        s = cmul(lam, s);
        s.x += x.x; s.y += x.y;
    }
    g_Sloc[((size_t)c * B_TOT + b) * P_TOT + p] = s;
}

// ---------------- K3: prefix combine across chunks ----------------
__global__ __launch_bounds__(256) void prefix_kernel() {
    int p = threadIdx.x;
    int b = blockIdx.x;  // B_TOT blocks
    float2 lamT = g_LamT[p];
    float2 s = make_float2(0.f, 0.f);
    for (int c = 0; c < C_CHK; c++) {
        g_init[((size_t)c * B_TOT + b) * P_TOT + p] = s;
        float2 sl = g_Sloc[((size_t)c * B_TOT + b) * P_TOT + p];
        s = cmul(lamT, s);
        s.x += sl.x; s.y += sl.y;
    }
}

// ---------------- K4: full scan with init, write o in-place over Bu ----------------
__global__ __launch_bounds__(256) void scan_final_kernel() {
    int p = threadIdx.x;
    int b = blockIdx.x % B_TOT;
    int c = blockIdx.x / B_TOT;
    float2 lam = g_Lam[p];
    float2 s = g_init[((size_t)c * B_TOT + b) * P_TOT + p];
    float2* base = g_Bu + ((size_t)(c * T_CHK) * B_TOT + b) * P_TOT + p;
    const size_t stride = (size_t)B_TOT * P_TOT;
#pragma unroll 4
    for (int t = 0; t < T_CHK; t++) {
        float2 x = base[t * stride];
        s = cmul(lam, s);
        s.x += x.x; s.y += x.y;
        base[t * stride] = s;
    }
}

// ---------------- launch ----------------
extern "C" void kernel_launch(void* const* d_in, const int* in_sizes, int n_in,
                              void* d_out, int out_size) {
    const float* u   = (const float*)d_in[0];
    const float* lLr = (const float*)d_in[1];
    const float* Li  = (const float*)d_in[2];
    const float* Br  = (const float*)d_in[3];
    const float* Bi  = (const float*)d_in[4];
    const float* Cr  = (const float*)d_in[5];
    const float* Ci  = (const float*)d_in[6];
    const float* Dv  = (const float*)d_in[7];
    const float* lDt = (const float*)d_in[8];
    float* out = (float*)d_out;

    void *pBu = nullptr, *pW1 = nullptr, *pW2 = nullptr;
    cudaGetSymbolAddress(&pBu, g_Bu);
    cudaGetSymbolAddress(&pW1, g_W1);
    cudaGetSymbolAddress(&pW2, g_W2);
    float* Bu = (float*)pBu;
    float* W1 = (float*)pW1;
    float* W2 = (float*)pW2;

    // K0: precompute
    precompute_kernel<<<1, 256>>>(lLr, Li, Br, Bi, Cr, Ci, lDt);

    // K1: Bu = u @ W1  (M=65536, K=128, N=512)
    gemm128_kernel<false><<<dim3(N1 / 128, M_TOT / 128), 256>>>(
        u, W1, Bu, M_TOT, N1, K1, nullptr, nullptr);

    // K2: local chunk scans
    scan_local_kernel<<<C_CHK * B_TOT, 256>>>();

    // K3: prefix combine
    prefix_kernel<<<B_TOT, 256>>>();

    // K4: final scan, o overwrites Bu
    scan_final_kernel<<<C_CHK * B_TOT, 256>>>();

    // K5: out = o @ W2 + D*u  (M=65536, K=512, N=128)
    gemm128_kernel<true><<<dim3(N2 / 128, M_TOT / 128), 256>>>(
        Bu, W2, out, M_TOT, N2, K2TOT, Dv, u);
}

// round 5
// speedup vs baseline: 1.6796x; 1.6796x over previous
#include <cuda_runtime.h>
#include <cuda_bf16.h>
#include <math.h>
#include <stdint.h>

// ---------------- problem constants ----------------
#define L_TOT 2048
#define B_TOT 32
#define H_TOT 128
#define P_TOT 256
#define T_CHK 64
#define C_CHK (L_TOT / T_CHK)       // 32 chunks
#define M_TOT (L_TOT * B_TOT)       // 65536 rows
#define NB2   512                   // Bu width in real floats (2*P)

// ---------------- scratch (device globals) ----------------
__device__ float    g_Bu[(size_t)M_TOT * NB2];     // 134 MB fp32 Bu -> consumed by scan
__device__ uint32_t g_ohw[(size_t)M_TOT * 256];    // o hi: bf16x2 words [m][256]
__device__ uint32_t g_olw[(size_t)M_TOT * 256];    // o lo
__device__ float2 g_Sloc[C_CHK * B_TOT * P_TOT];
__device__ float2 g_init[C_CHK * B_TOT * P_TOT];
__device__ float2 g_Lam[P_TOT];
__device__ float2 g_LamT[P_TOT];
__device__ float2 g_coeff[P_TOT];
// Split-K packed weights (row-major [n][k'])
__device__ __nv_bfloat16 g_W1p[512 * 384];         // B' for GEMM1: [Bh|Bh|Bl] along k'
__device__ __nv_bfloat16 g_W2p[128 * 1536];        // B' for GEMM2

// ---------------- helpers ----------------
__device__ __forceinline__ void split_bf16(float v, __nv_bfloat16& h, __nv_bfloat16& l) {
    h = __float2bfloat16(v);
    l = __float2bfloat16(v - __bfloat162float(h));
}
__device__ __forceinline__ __nv_bfloat16 bf_hi(float v) { return __float2bfloat16(v); }
__device__ __forceinline__ __nv_bfloat16 bf_lo(float v) {
    __nv_bfloat16 h = __float2bfloat16(v);
    return __float2bfloat16(v - __bfloat162float(h));
}
__device__ __forceinline__ float2 cmul(float2 a, float2 b) {
    return make_float2(a.x * b.x - a.y * b.y, a.x * b.y + a.y * b.x);
}
__device__ __forceinline__ void mma16816(float* d, const uint32_t* a, const uint32_t* b) {
    asm volatile(
        "mma.sync.aligned.m16n8k16.row.col.f32.bf16.bf16.f32 "
        "{%0,%1,%2,%3}, {%4,%5,%6,%7}, {%8,%9}, {%0,%1,%2,%3};"
        : "+f"(d[0]), "+f"(d[1]), "+f"(d[2]), "+f"(d[3])
        : "r"(a[0]), "r"(a[1]), "r"(a[2]), "r"(a[3]), "r"(b[0]), "r"(b[1]));
}

// ---------------- K0a: per-p scalar precompute ----------------
__global__ void precompute_a(const float* __restrict__ lLr, const float* __restrict__ Li,
                             const float* __restrict__ lDelta) {
    int p = threadIdx.x;
    double lamr = -exp((double)lLr[p]);
    double lami = (double)Li[p];
    double dt = exp((double)lDelta[p]);
    double lbr = lamr * dt, lbi = lami * dt;
    double er = exp(lbr);
    double Lr = er * cos(lbi), Limg = er * sin(lbi);
    g_Lam[p] = make_float2((float)Lr, (float)Limg);
    double eT = exp((double)T_CHK * lbr);
    g_LamT[p] = make_float2((float)(eT * cos((double)T_CHK * lbi)),
                            (float)(eT * sin((double)T_CHK * lbi)));
    double nr = Lr - 1.0, ni = Limg;
    double den = lamr * lamr + lami * lami;
    g_coeff[p] = make_float2((float)((nr * lamr + ni * lami) / den),
                             (float)((ni * lamr - nr * lami) / den));
}

// ---------------- K0b: pack split-K weights ----------------
__global__ __launch_bounds__(256) void precompute_w(
    const float* __restrict__ Br, const float* __restrict__ Bi,
    const float* __restrict__ Cr, const float* __restrict__ Ci) {
    int idx = blockIdx.x * 256 + threadIdx.x;  // 32768 = 128 h x 256 p
    int h = idx >> 8, p = idx & 255;
    float2 cf = g_coeff[p];
    float br = Br[p * H_TOT + h], bi = Bi[p * H_TOT + h];
    float w1v[2] = {cf.x * br - cf.y * bi, cf.x * bi + cf.y * br};
#pragma unroll
    for (int j = 0; j < 2; j++) {
        int n = 2 * p + j;
        __nv_bfloat16 hh, ll;
        split_bf16(w1v[j], hh, ll);
        g_W1p[(size_t)n * 384 + h]       = hh;   // pass0: Ah*Bh
        g_W1p[(size_t)n * 384 + 128 + h] = hh;   // pass1: Al*Bh
        g_W1p[(size_t)n * 384 + 256 + h] = ll;   // pass2: Ah*Bl
    }
    float w2v[2] = {Cr[h * P_TOT + p], -Ci[h * P_TOT + p]};
#pragma unroll
    for (int j = 0; j < 2; j++) {
        int k = 2 * p + j;
        __nv_bfloat16 hh, ll;
        split_bf16(w2v[j], hh, ll);
        g_W2p[(size_t)h * 1536 + k]        = hh;
        g_W2p[(size_t)h * 1536 + 512 + k]  = hh;
        g_W2p[(size_t)h * 1536 + 1024 + k] = ll;
    }
}

// ---------------- GEMM1: Bu = u @ W1'  (M=65536, N=512, K'=384) ----------------
__global__ __launch_bounds__(256, 2) void gemm1_mma(const float* __restrict__ u) {
    __shared__ __align__(16) __nv_bfloat16 As[128][40];
    __shared__ __align__(16) __nv_bfloat16 Bs[128][40];
    int tid = threadIdx.x, lane = tid & 31, wid = tid >> 5;
    int gq = lane >> 2, tig = lane & 3;
    int wm = wid >> 1, wn = wid & 1;
    int bn = blockIdx.x * 128, bm = blockIdx.y * 128;

    float acc[2][8][4];
#pragma unroll
    for (int mt = 0; mt < 2; mt++)
#pragma unroll
        for (int nt = 0; nt < 8; nt++)
#pragma unroll
            for (int i = 0; i < 4; i++) acc[mt][nt][i] = 0.f;

    for (int kt = 0; kt < 12; kt++) {
        int pass = kt >> 2;
        int kb = (kt & 3) * 32;
        __syncthreads();
        // A': u fp32 tile 128x32 -> bf16 hi (pass 0/2) or lo (pass 1)
#pragma unroll
        for (int it = 0; it < 4; it++) {
            int idx = tid + it * 256;
            int row = idx >> 3, kc = (idx & 7) * 4;
            float4 v = *(const float4*)(u + (size_t)(bm + row) * 128 + kb + kc);
            __nv_bfloat162 w0, w1;
            if (pass == 1) {
                w0.x = bf_lo(v.x); w0.y = bf_lo(v.y);
                w1.x = bf_lo(v.z); w1.y = bf_lo(v.w);
            } else {
                w0.x = bf_hi(v.x); w0.y = bf_hi(v.y);
                w1.x = bf_hi(v.z); w1.y = bf_hi(v.w);
            }
            *(uint2*)&As[row][kc] = make_uint2(*(uint32_t*)&w0, *(uint32_t*)&w1);
        }
        // B' tile 128 n-rows x 32 k
#pragma unroll
        for (int it = 0; it < 2; it++) {
            int idx = tid + it * 256;
            int row = idx >> 2, q = idx & 3;
            *(uint4*)&Bs[row][q * 8] =
                *(const uint4*)(g_W1p + (size_t)(bn + row) * 384 + kt * 32 + q * 8);
        }
        __syncthreads();
#pragma unroll
        for (int kk = 0; kk < 2; kk++) {
            int k16 = kk * 16;
            uint32_t a[2][4], b[8][2];
#pragma unroll
            for (int mt = 0; mt < 2; mt++) {
                int r = wm * 32 + mt * 16 + gq;
                a[mt][0] = *(uint32_t*)&As[r][k16 + 2 * tig];
                a[mt][1] = *(uint32_t*)&As[r + 8][k16 + 2 * tig];
                a[mt][2] = *(uint32_t*)&As[r][k16 + 8 + 2 * tig];
                a[mt][3] = *(uint32_t*)&As[r + 8][k16 + 8 + 2 * tig];
            }
#pragma unroll
            for (int nt = 0; nt < 8; nt++) {
                int c = wn * 64 + nt * 8 + gq;
                b[nt][0] = *(uint32_t*)&Bs[c][k16 + 2 * tig];
                b[nt][1] = *(uint32_t*)&Bs[c][k16 + 8 + 2 * tig];
            }
#pragma unroll
            for (int mt = 0; mt < 2; mt++)
#pragma unroll
                for (int nt = 0; nt < 8; nt++)
                    mma16816(acc[mt][nt], a[mt], b[nt]);
        }
    }
    // epilogue: fp32 Bu [m][512]
#pragma unroll
    for (int mt = 0; mt < 2; mt++)
#pragma unroll
        for (int nt = 0; nt < 8; nt++) {
            int r = bm + wm * 32 + mt * 16 + gq;
            int c = bn + wn * 64 + nt * 8 + 2 * tig;
            *(float2*)&g_Bu[(size_t)r * NB2 + c] =
                make_float2(acc[mt][nt][0], acc[mt][nt][1]);
            *(float2*)&g_Bu[(size_t)(r + 8) * NB2 + c] =
                make_float2(acc[mt][nt][2], acc[mt][nt][3]);
        }
}

// ---------------- K2: per-chunk local scan ----------------
__global__ __launch_bounds__(256) void scan_local_kernel() {
    int p = threadIdx.x;
    int b = blockIdx.x % B_TOT;
    int c = blockIdx.x / B_TOT;
    float2 lam = g_Lam[p];
    float2 s = make_float2(0.f, 0.f);
    const float2* base = (const float2*)g_Bu + ((size_t)(c * T_CHK) * B_TOT + b) * P_TOT + p;
    const size_t stride = (size_t)B_TOT * P_TOT;
#pragma unroll 8
    for (int t = 0; t < T_CHK; t++) {
        float2 x = base[t * stride];
        s = cmul(lam, s);
        s.x += x.x; s.y += x.y;
    }
    g_Sloc[((size_t)c * B_TOT + b) * P_TOT + p] = s;
}

// ---------------- K3: prefix combine (preloaded, register chain) ----------------
__global__ __launch_bounds__(256) void prefix_kernel() {
    int p = threadIdx.x;
    int b = blockIdx.x;
    float2 lamT = g_LamT[p];
    float2 vals[C_CHK];
#pragma unroll
    for (int c = 0; c < C_CHK; c++)
        vals[c] = g_Sloc[((size_t)c * B_TOT + b) * P_TOT + p];
    float2 s = make_float2(0.f, 0.f);
#pragma unroll
    for (int c = 0; c < C_CHK; c++) {
        g_init[((size_t)c * B_TOT + b) * P_TOT + p] = s;
        s = cmul(lamT, s);
        s.x += vals[c].x; s.y += vals[c].y;
    }
}

// ---------------- K4: final scan, emit o as bf16 hi/lo words ----------------
__global__ __launch_bounds__(256) void scan_final_kernel() {
    int p = threadIdx.x;
    int b = blockIdx.x % B_TOT;
    int c = blockIdx.x / B_TOT;
    float2 lam = g_Lam[p];
    float2 s = g_init[((size_t)c * B_TOT + b) * P_TOT + p];
    const float2* base = (const float2*)g_Bu + ((size_t)(c * T_CHK) * B_TOT + b) * P_TOT + p;
    const size_t stride = (size_t)B_TOT * P_TOT;
#pragma unroll 8
    for (int t = 0; t < T_CHK; t++) {
        float2 x = base[t * stride];
        s = cmul(lam, s);
        s.x += x.x; s.y += x.y;
        size_t m = (size_t)(c * T_CHK + t) * B_TOT + b;
        __nv_bfloat162 hh, ll;
        split_bf16(s.x, hh.x, ll.x);
        split_bf16(s.y, hh.y, ll.y);
        g_ohw[m * 256 + p] = *(uint32_t*)&hh;
        g_olw[m * 256 + p] = *(uint32_t*)&ll;
    }
}

// ---------------- GEMM2: out = o @ W2' + D*u  (M=65536, N=128, K'=1536) ----------------
__global__ __launch_bounds__(256, 2) void gemm2_mma(const float* __restrict__ u,
                                                    const float* __restrict__ Dv,
                                                    float* __restrict__ out) {
    __shared__ __align__(16) __nv_bfloat16 As[128][40];
    __shared__ __align__(16) __nv_bfloat16 Bs[128][40];
    int tid = threadIdx.x, lane = tid & 31, wid = tid >> 5;
    int gq = lane >> 2, tig = lane & 3;
    int wm = wid >> 1, wn = wid & 1;
    int bm = blockIdx.x * 128;

    float acc[2][8][4];
#pragma unroll
    for (int mt = 0; mt < 2; mt++)
#pragma unroll
        for (int nt = 0; nt < 8; nt++)
#pragma unroll
            for (int i = 0; i < 4; i++) acc[mt][nt][i] = 0.f;

    for (int kt = 0; kt < 48; kt++) {
        int pass = kt >> 4;
        int wb = (kt & 15) * 16;   // word base within 256 bf16x2 words
        const uint32_t* srcA = (pass == 1) ? g_olw : g_ohw;
        __syncthreads();
        // A' tile: 128 rows x 16 words (32 bf16)
#pragma unroll
        for (int it = 0; it < 2; it++) {
            int idx = tid + it * 256;
            int row = idx >> 2, w4 = (idx & 3) * 4;
            uint4 v = *(const uint4*)(srcA + (size_t)(bm + row) * 256 + wb + w4);
            *(uint4*)&As[row][w4 * 2] = v;
        }
        // B' tile: 128 n-rows x 32 k
#pragma unroll
        for (int it = 0; it < 2; it++) {
            int idx = tid + it * 256;
            int row = idx >> 2, q = idx & 3;
            *(uint4*)&Bs[row][q * 8] =
                *(const uint4*)(g_W2p + (size_t)row * 1536 + kt * 32 + q * 8);
        }
        __syncthreads();
#pragma unroll
        for (int kk = 0; kk < 2; kk++) {
            int k16 = kk * 16;
            uint32_t a[2][4], b[8][2];
#pragma unroll
            for (int mt = 0; mt < 2; mt++) {
                int r = wm * 32 + mt * 16 + gq;
                a[mt][0] = *(uint32_t*)&As[r][k16 + 2 * tig];
                a[mt][1] = *(uint32_t*)&As[r + 8][k16 + 2 * tig];
                a[mt][2] = *(uint32_t*)&As[r][k16 + 8 + 2 * tig];
                a[mt][3] = *(uint32_t*)&As[r + 8][k16 + 8 + 2 * tig];
            }
#pragma unroll
            for (int nt = 0; nt < 8; nt++) {
                int c = wn * 64 + nt * 8 + gq;
                b[nt][0] = *(uint32_t*)&Bs[c][k16 + 2 * tig];
                b[nt][1] = *(uint32_t*)&Bs[c][k16 + 8 + 2 * tig];
            }
#pragma unroll
            for (int mt = 0; mt < 2; mt++)
#pragma unroll
                for (int nt = 0; nt < 8; nt++)
                    mma16816(acc[mt][nt], a[mt], b[nt]);
        }
    }
    // epilogue: out = acc + D*u
#pragma unroll
    for (int mt = 0; mt < 2; mt++)
#pragma unroll
        for (int nt = 0; nt < 8; nt++) {
            int c = wn * 64 + nt * 8 + 2 * tig;
            float2 dv = *(const float2*)(Dv + c);
#pragma unroll
            for (int half = 0; half < 2; half++) {
                int r = bm + wm * 32 + mt * 16 + gq + half * 8;
                float2 uv = *(const float2*)(u + (size_t)r * 128 + c);
                float2 o;
                o.x = acc[mt][nt][2 * half + 0] + dv.x * uv.x;
                o.y = acc[mt][nt][2 * half + 1] + dv.y * uv.y;
                *(float2*)&out[(size_t)r * 128 + c] = o;
            }
        }
}

// ---------------- launch ----------------
extern "C" void kernel_launch(void* const* d_in, const int* in_sizes, int n_in,
                              void* d_out, int out_size) {
    const float* u   = (const float*)d_in[0];
    const float* lLr = (const float*)d_in[1];
    const float* Li  = (const float*)d_in[2];
    const float* Br  = (const float*)d_in[3];
    const float* Bi  = (const float*)d_in[4];
    const float* Cr  = (const float*)d_in[5];
    const float* Ci  = (const float*)d_in[6];
    const float* Dv  = (const float*)d_in[7];
    const float* lDt = (const float*)d_in[8];
    float* out = (float*)d_out;

    precompute_a<<<1, 256>>>(lLr, Li, lDt);
    precompute_w<<<128, 256>>>(Br, Bi, Cr, Ci);

    gemm1_mma<<<dim3(4, M_TOT / 128), 256>>>(u);

    scan_local_kernel<<<C_CHK * B_TOT, 256>>>();
    prefix_kernel<<<B_TOT, 256>>>();
    scan_final_kernel<<<C_CHK * B_TOT, 256>>>();

    gemm2_mma<<<M_TOT / 128, 256>>>(u, Dv, out);
}

// round 6
// speedup vs baseline: 2.2619x; 1.3467x over previous
#include <cuda_runtime.h>
#include <cuda_bf16.h>
#include <math.h>
#include <stdint.h>

// ---------------- problem constants ----------------
#define L_TOT 2048
#define B_TOT 32
#define H_TOT 128
#define P_TOT 256
#define T_CHK 64
#define C_CHK (L_TOT / T_CHK)       // 32 chunks
#define M_TOT (L_TOT * B_TOT)       // 65536 rows
#define NB2   512                   // Bu width in real floats (2*P)

// ---------------- scratch (device globals) ----------------
__device__ float    g_Bu[(size_t)M_TOT * NB2];     // 134 MB fp32 Bu -> consumed by scan
__device__ uint32_t g_ohw[(size_t)M_TOT * 256];    // o hi: bf16x2 words [m][256]
__device__ uint32_t g_olw[(size_t)M_TOT * 256];    // o lo
__device__ float2 g_Sloc[C_CHK * B_TOT * P_TOT];
__device__ float2 g_init[C_CHK * B_TOT * P_TOT];
__device__ float2 g_Lam[P_TOT];
__device__ float2 g_LamT[P_TOT];
__device__ float2 g_coeff[P_TOT];
// weights: separate hi/lo planes, n-major [n][k]
__device__ __nv_bfloat16 g_W1h[512 * 128];
__device__ __nv_bfloat16 g_W1l[512 * 128];
__device__ __nv_bfloat16 g_W2h[128 * 512];
__device__ __nv_bfloat16 g_W2l[128 * 512];

// ---------------- helpers ----------------
__device__ __forceinline__ void split_bf16(float v, __nv_bfloat16& h, __nv_bfloat16& l) {
    h = __float2bfloat16(v);
    l = __float2bfloat16(v - __bfloat162float(h));
}
__device__ __forceinline__ float2 cmul(float2 a, float2 b) {
    return make_float2(a.x * b.x - a.y * b.y, a.x * b.y + a.y * b.x);
}
__device__ __forceinline__ void mma16816(float* d, const uint32_t* a, const uint32_t* b) {
    asm volatile(
        "mma.sync.aligned.m16n8k16.row.col.f32.bf16.bf16.f32 "
        "{%0,%1,%2,%3}, {%4,%5,%6,%7}, {%8,%9}, {%0,%1,%2,%3};"
        : "+f"(d[0]), "+f"(d[1]), "+f"(d[2]), "+f"(d[3])
        : "r"(a[0]), "r"(a[1]), "r"(a[2]), "r"(a[3]), "r"(b[0]), "r"(b[1]));
}
__device__ __forceinline__ uint32_t smem_u32(const void* p) {
    uint32_t a;
    asm("{ .reg .u64 t; cvta.to.shared.u64 t, %1; cvt.u32.u64 %0, t; }" : "=r"(a) : "l"(p));
    return a;
}
#define CP_ASYNC16(dst, src) \
    asm volatile("cp.async.cg.shared.global [%0], [%1], 16;" :: "r"(dst), "l"(src))
#define CP_COMMIT() asm volatile("cp.async.commit_group;" ::: "memory")
#define CP_WAIT0()  asm volatile("cp.async.wait_group 0;" ::: "memory")

// SMEM tile geometry: rows of 40 bf16 (80 B, 16B-aligned stride), 128 rows/tile
#define TILE_B (128 * 40 * 2)      // 10240 B
#define OF_AH 0
#define OF_AL TILE_B
#define OF_BH (2 * TILE_B)
#define OF_BL (3 * TILE_B)
#define BUF_B (4 * TILE_B)         // 40960 B per stage
#define SMEM_TOTAL (2 * BUF_B)     // 81920 B

// ---------------- K0a: per-p scalar precompute ----------------
__global__ void precompute_a(const float* __restrict__ lLr, const float* __restrict__ Li,
                             const float* __restrict__ lDelta) {
    int p = threadIdx.x;
    double lamr = -exp((double)lLr[p]);
    double lami = (double)Li[p];
    double dt = exp((double)lDelta[p]);
    double lbr = lamr * dt, lbi = lami * dt;
    double er = exp(lbr);
    double Lr = er * cos(lbi), Limg = er * sin(lbi);
    g_Lam[p] = make_float2((float)Lr, (float)Limg);
    double eT = exp((double)T_CHK * lbr);
    g_LamT[p] = make_float2((float)(eT * cos((double)T_CHK * lbi)),
                            (float)(eT * sin((double)T_CHK * lbi)));
    double nr = Lr - 1.0, ni = Limg;
    double den = lamr * lamr + lami * lami;
    g_coeff[p] = make_float2((float)((nr * lamr + ni * lami) / den),
                             (float)((ni * lamr - nr * lami) / den));
}

// ---------------- K0b: pack weights into hi/lo planes ----------------
__global__ __launch_bounds__(256) void precompute_w(
    const float* __restrict__ Br, const float* __restrict__ Bi,
    const float* __restrict__ Cr, const float* __restrict__ Ci) {
    int idx = blockIdx.x * 256 + threadIdx.x;  // 32768 = 128 h x 256 p
    int h = idx >> 8, p = idx & 255;
    float2 cf = g_coeff[p];
    float br = Br[p * H_TOT + h], bi = Bi[p * H_TOT + h];
    float w1v[2] = {cf.x * br - cf.y * bi, cf.x * bi + cf.y * br};
#pragma unroll
    for (int j = 0; j < 2; j++) {
        int n = 2 * p + j;
        __nv_bfloat16 hh, ll;
        split_bf16(w1v[j], hh, ll);
        g_W1h[(size_t)n * 128 + h] = hh;
        g_W1l[(size_t)n * 128 + h] = ll;
    }
    float w2v[2] = {Cr[h * P_TOT + p], -Ci[h * P_TOT + p]};
#pragma unroll
    for (int j = 0; j < 2; j++) {
        int k = 2 * p + j;
        __nv_bfloat16 hh, ll;
        split_bf16(w2v[j], hh, ll);
        g_W2h[(size_t)h * 512 + k] = hh;
        g_W2l[(size_t)h * 512 + k] = ll;
    }
}

// ---------------- shared MMA inner step (both GEMMs) ----------------
// acc += Ah*Bh + Al*Bh + Ah*Bl over one 32-wide K chunk in buffer `base`
__device__ __forceinline__ void mma_chunk(const char* base, int wm, int wn, int gq, int tig,
                                          float acc[2][8][4]) {
    const __nv_bfloat16* Ah = (const __nv_bfloat16*)(base + OF_AH);
    const __nv_bfloat16* Al = (const __nv_bfloat16*)(base + OF_AL);
    const __nv_bfloat16* Bh = (const __nv_bfloat16*)(base + OF_BH);
    const __nv_bfloat16* Bl = (const __nv_bfloat16*)(base + OF_BL);
#pragma unroll
    for (int kk = 0; kk < 2; kk++) {
        int k16 = kk * 16;
        uint32_t ah[2][4], al[2][4];
#pragma unroll
        for (int mt = 0; mt < 2; mt++) {
            int r = wm * 32 + mt * 16 + gq;
            int o0 = r * 40 + k16 + 2 * tig;
            int o1 = (r + 8) * 40 + k16 + 2 * tig;
            ah[mt][0] = *(const uint32_t*)&Ah[o0];
            ah[mt][1] = *(const uint32_t*)&Ah[o1];
            ah[mt][2] = *(const uint32_t*)&Ah[o0 + 8];
            ah[mt][3] = *(const uint32_t*)&Ah[o1 + 8];
            al[mt][0] = *(const uint32_t*)&Al[o0];
            al[mt][1] = *(const uint32_t*)&Al[o1];
            al[mt][2] = *(const uint32_t*)&Al[o0 + 8];
            al[mt][3] = *(const uint32_t*)&Al[o1 + 8];
        }
        // pass over Bh: Ah*Bh + Al*Bh
        {
            uint32_t b[8][2];
#pragma unroll
            for (int nt = 0; nt < 8; nt++) {
                int c = wn * 64 + nt * 8 + gq;
                b[nt][0] = *(const uint32_t*)&Bh[c * 40 + k16 + 2 * tig];
                b[nt][1] = *(const uint32_t*)&Bh[c * 40 + k16 + 8 + 2 * tig];
            }
#pragma unroll
            for (int mt = 0; mt < 2; mt++)
#pragma unroll
                for (int nt = 0; nt < 8; nt++) {
                    mma16816(acc[mt][nt], ah[mt], b[nt]);
                    mma16816(acc[mt][nt], al[mt], b[nt]);
                }
        }
        // pass over Bl: Ah*Bl
        {
            uint32_t b[8][2];
#pragma unroll
            for (int nt = 0; nt < 8; nt++) {
                int c = wn * 64 + nt * 8 + gq;
                b[nt][0] = *(const uint32_t*)&Bl[c * 40 + k16 + 2 * tig];
                b[nt][1] = *(const uint32_t*)&Bl[c * 40 + k16 + 8 + 2 * tig];
            }
#pragma unroll
            for (int mt = 0; mt < 2; mt++)
#pragma unroll
                for (int nt = 0; nt < 8; nt++)
                    mma16816(acc[mt][nt], ah[mt], b[nt]);
        }
    }
}

// ---------------- GEMM1: Bu = u @ W1 (M=65536, N=512, K=128; 4 kt) ----------------
__global__ __launch_bounds__(256, 2) void gemm1_mma(const float* __restrict__ u) {
    extern __shared__ char smem[];
    uint32_t sb = smem_u32(smem);
    int tid = threadIdx.x, lane = tid & 31, wid = tid >> 5;
    int gq = lane >> 2, tig = lane & 3;
    int wm = wid >> 1, wn = wid & 1;
    int bn = blockIdx.x * 128, bm = blockIdx.y * 128;

    float acc[2][8][4];
#pragma unroll
    for (int mt = 0; mt < 2; mt++)
#pragma unroll
        for (int nt = 0; nt < 8; nt++)
#pragma unroll
            for (int i = 0; i < 4; i++) acc[mt][nt][i] = 0.f;

    float4 areg[4];
    // prologue: A regs for kt=0, B cp.async for kt=0 into buf 0
#pragma unroll
    for (int i = 0; i < 4; i++) {
        int idx = tid + i * 256;
        int row = idx >> 3, c4 = (idx & 7) * 4;
        areg[i] = *(const float4*)(u + (size_t)(bm + row) * 128 + 0 + c4);
    }
#pragma unroll
    for (int i = 0; i < 2; i++) {
        int idx = tid + i * 256;
        int row = idx >> 2, seg = idx & 3;
        CP_ASYNC16(sb + OF_BH + row * 80 + seg * 16,
                   g_W1h + (size_t)(bn + row) * 128 + seg * 8);
        CP_ASYNC16(sb + OF_BL + row * 80 + seg * 16,
                   g_W1l + (size_t)(bn + row) * 128 + seg * 8);
    }
    CP_COMMIT();

    for (int kt = 0; kt < 4; kt++) {
        int b = kt & 1;
        char* buf = smem + b * BUF_B;
        // STS A (convert regs) into current buffer
#pragma unroll
        for (int i = 0; i < 4; i++) {
            int idx = tid + i * 256;
            int row = idx >> 3, c4 = (idx & 7) * 4;
            float4 v = areg[i];
            __nv_bfloat162 h01, h23, l01, l23;
            split_bf16(v.x, h01.x, l01.x);
            split_bf16(v.y, h01.y, l01.y);
            split_bf16(v.z, h23.x, l23.x);
            split_bf16(v.w, h23.y, l23.y);
            *(uint2*)(buf + OF_AH + row * 80 + c4 * 2) =
                make_uint2(*(uint32_t*)&h01, *(uint32_t*)&h23);
            *(uint2*)(buf + OF_AL + row * 80 + c4 * 2) =
                make_uint2(*(uint32_t*)&l01, *(uint32_t*)&l23);
        }
        // prefetch next A into regs
        if (kt < 3) {
#pragma unroll
            for (int i = 0; i < 4; i++) {
                int idx = tid + i * 256;
                int row = idx >> 3, c4 = (idx & 7) * 4;
                areg[i] = *(const float4*)(u + (size_t)(bm + row) * 128 + (kt + 1) * 32 + c4);
            }
        }
        CP_WAIT0();
        __syncthreads();
        // issue next B into alternate buffer
        if (kt < 3) {
            uint32_t nb = sb + (b ^ 1) * BUF_B;
#pragma unroll
            for (int i = 0; i < 2; i++) {
                int idx = tid + i * 256;
                int row = idx >> 2, seg = idx & 3;
                CP_ASYNC16(nb + OF_BH + row * 80 + seg * 16,
                           g_W1h + (size_t)(bn + row) * 128 + (kt + 1) * 32 + seg * 8);
                CP_ASYNC16(nb + OF_BL + row * 80 + seg * 16,
                           g_W1l + (size_t)(bn + row) * 128 + (kt + 1) * 32 + seg * 8);
            }
            CP_COMMIT();
        }
        mma_chunk(buf, wm, wn, gq, tig, acc);
    }
    // epilogue: Bu fp32 [m][512]
#pragma unroll
    for (int mt = 0; mt < 2; mt++)
#pragma unroll
        for (int nt = 0; nt < 8; nt++) {
            int r = bm + wm * 32 + mt * 16 + gq;
            int c = bn + wn * 64 + nt * 8 + 2 * tig;
            *(float2*)&g_Bu[(size_t)r * NB2 + c] = make_float2(acc[mt][nt][0], acc[mt][nt][1]);
            *(float2*)&g_Bu[(size_t)(r + 8) * NB2 + c] = make_float2(acc[mt][nt][2], acc[mt][nt][3]);
        }
}

// ---------------- K2: per-chunk local scan ----------------
__global__ __launch_bounds__(256) void scan_local_kernel() {
    int p = threadIdx.x;
    int b = blockIdx.x % B_TOT;
    int c = blockIdx.x / B_TOT;
    float2 lam = g_Lam[p];
    float2 s = make_float2(0.f, 0.f);
    const float2* base = (const float2*)g_Bu + ((size_t)(c * T_CHK) * B_TOT + b) * P_TOT + p;
    const size_t stride = (size_t)B_TOT * P_TOT;
#pragma unroll 8
    for (int t = 0; t < T_CHK; t++) {
        float2 x = base[t * stride];
        s = cmul(lam, s);
        s.x += x.x; s.y += x.y;
    }
    g_Sloc[((size_t)c * B_TOT + b) * P_TOT + p] = s;
}

// ---------------- K3: prefix combine ----------------
__global__ __launch_bounds__(256) void prefix_kernel() {
    int p = threadIdx.x;
    int b = blockIdx.x;
    float2 lamT = g_LamT[p];
    float2 vals[C_CHK];
#pragma unroll
    for (int c = 0; c < C_CHK; c++)
        vals[c] = g_Sloc[((size_t)c * B_TOT + b) * P_TOT + p];
    float2 s = make_float2(0.f, 0.f);
#pragma unroll
    for (int c = 0; c < C_CHK; c++) {
        g_init[((size_t)c * B_TOT + b) * P_TOT + p] = s;
        s = cmul(lamT, s);
        s.x += vals[c].x; s.y += vals[c].y;
    }
}

// ---------------- K4: final scan, emit o as bf16 hi/lo words ----------------
__global__ __launch_bounds__(256) void scan_final_kernel() {
    int p = threadIdx.x;
    int b = blockIdx.x % B_TOT;
    int c = blockIdx.x / B_TOT;
    float2 lam = g_Lam[p];
    float2 s = g_init[((size_t)c * B_TOT + b) * P_TOT + p];
    const float2* base = (const float2*)g_Bu + ((size_t)(c * T_CHK) * B_TOT + b) * P_TOT + p;
    const size_t stride = (size_t)B_TOT * P_TOT;
#pragma unroll 8
    for (int t = 0; t < T_CHK; t++) {
        float2 x = base[t * stride];
        s = cmul(lam, s);
        s.x += x.x; s.y += x.y;
        size_t m = (size_t)(c * T_CHK + t) * B_TOT + b;
        __nv_bfloat162 hh, ll;
        split_bf16(s.x, hh.x, ll.x);
        split_bf16(s.y, hh.y, ll.y);
        g_ohw[m * 256 + p] = *(uint32_t*)&hh;
        g_olw[m * 256 + p] = *(uint32_t*)&ll;
    }
}

// ---------------- GEMM2: out = o @ W2 + D*u (M=65536, N=128, K=512; 16 kt) ----------------
__global__ __launch_bounds__(256, 2) void gemm2_mma(const float* __restrict__ u,
                                                    const float* __restrict__ Dv,
                                                    float* __restrict__ out) {
    extern __shared__ char smem[];
    uint32_t sb = smem_u32(smem);
    int tid = threadIdx.x, lane = tid & 31, wid = tid >> 5;
    int gq = lane >> 2, tig = lane & 3;
    int wm = wid >> 1, wn = wid & 1;
    int bm = blockIdx.x * 128;

    float acc[2][8][4];
#pragma unroll
    for (int mt = 0; mt < 2; mt++)
#pragma unroll
        for (int nt = 0; nt < 8; nt++)
#pragma unroll
            for (int i = 0; i < 4; i++) acc[mt][nt][i] = 0.f;

    // prologue: all 4 tiles for kt=0 into buf 0
#pragma unroll
    for (int i = 0; i < 2; i++) {
        int idx = tid + i * 256;
        int row = idx >> 2, seg = idx & 3;
        CP_ASYNC16(sb + OF_AH + row * 80 + seg * 16, g_ohw + (size_t)(bm + row) * 256 + seg * 4);
        CP_ASYNC16(sb + OF_AL + row * 80 + seg * 16, g_olw + (size_t)(bm + row) * 256 + seg * 4);
        CP_ASYNC16(sb + OF_BH + row * 80 + seg * 16, g_W2h + (size_t)row * 512 + seg * 8);
        CP_ASYNC16(sb + OF_BL + row * 80 + seg * 16, g_W2l + (size_t)row * 512 + seg * 8);
    }
    CP_COMMIT();

    for (int kt = 0; kt < 16; kt++) {
        int b = kt & 1;
        CP_WAIT0();
        __syncthreads();
        if (kt < 15) {
            uint32_t nb = sb + (b ^ 1) * BUF_B;
            int kn = kt + 1;
#pragma unroll
            for (int i = 0; i < 2; i++) {
                int idx = tid + i * 256;
                int row = idx >> 2, seg = idx & 3;
                CP_ASYNC16(nb + OF_AH + row * 80 + seg * 16,
                           g_ohw + (size_t)(bm + row) * 256 + kn * 16 + seg * 4);
                CP_ASYNC16(nb + OF_AL + row * 80 + seg * 16,
                           g_olw + (size_t)(bm + row) * 256 + kn * 16 + seg * 4);
                CP_ASYNC16(nb + OF_BH + row * 80 + seg * 16,
                           g_W2h + (size_t)row * 512 + kn * 32 + seg * 8);
                CP_ASYNC16(nb + OF_BL + row * 80 + seg * 16,
                           g_W2l + (size_t)row * 512 + kn * 32 + seg * 8);
            }
            CP_COMMIT();
        }
        mma_chunk(smem + b * BUF_B, wm, wn, gq, tig, acc);
    }
    // epilogue: out = acc + D*u
#pragma unroll
    for (int mt = 0; mt < 2; mt++)
#pragma unroll
        for (int nt = 0; nt < 8; nt++) {
            int c = wn * 64 + nt * 8 + 2 * tig;
            float2 dv = *(const float2*)(Dv + c);
#pragma unroll
            for (int half = 0; half < 2; half++) {
                int r = bm + wm * 32 + mt * 16 + gq + half * 8;
                float2 uv = *(const float2*)(u + (size_t)r * 128 + c);
                float2 o;
                o.x = acc[mt][nt][2 * half + 0] + dv.x * uv.x;
                o.y = acc[mt][nt][2 * half + 1] + dv.y * uv.y;
                *(float2*)&out[(size_t)r * 128 + c] = o;
            }
        }
}

// ---------------- launch ----------------
extern "C" void kernel_launch(void* const* d_in, const int* in_sizes, int n_in,
                              void* d_out, int out_size) {
    const float* u   = (const float*)d_in[0];
    const float* lLr = (const float*)d_in[1];
    const float* Li  = (const float*)d_in[2];
    const float* Br  = (const float*)d_in[3];
    const float* Bi  = (const float*)d_in[4];
    const float* Cr  = (const float*)d_in[5];
    const float* Ci  = (const float*)d_in[6];
    const float* Dv  = (const float*)d_in[7];
    const float* lDt = (const float*)d_in[8];
    float* out = (float*)d_out;

    cudaFuncSetAttribute(gemm1_mma, cudaFuncAttributeMaxDynamicSharedMemorySize, SMEM_TOTAL);
    cudaFuncSetAttribute(gemm2_mma, cudaFuncAttributeMaxDynamicSharedMemorySize, SMEM_TOTAL);

    precompute_a<<<1, 256>>>(lLr, Li, lDt);
    precompute_w<<<128, 256>>>(Br, Bi, Cr, Ci);

    gemm1_mma<<<dim3(4, M_TOT / 128), 256, SMEM_TOTAL>>>(u);

    scan_local_kernel<<<C_CHK * B_TOT, 256>>>();
    prefix_kernel<<<B_TOT, 256>>>();
    scan_final_kernel<<<C_CHK * B_TOT, 256>>>();

    gemm2_mma<<<M_TOT / 128, 256, SMEM_TOTAL>>>(u, Dv, out);
}